// round 9
// baseline (speedup 1.0000x reference)
#include <cuda_runtime.h>

#define N_NODES 50000
#define N_EDGES 800000
#define D_FEAT  64
#define UNITS   64
#define CAP     64          // Poisson(16): P(deg >= 64) ~ 1e-20

#define GEMM_BLOCKS ((N_NODES + 63) / 64)          // 782
#define SCAT_BLOCKS ((N_EDGES / 4 + 255) / 256)    // 782

typedef unsigned long long ull;

// ---------------------------------------------------------------------------
// Scratch (__device__ globals; allocation-free rule).
// g_count starts zero-initialized at module load and is re-zeroed at the end
// of every k_agg_relu call -> every kernel_launch sees zeroed counters.
// ---------------------------------------------------------------------------
__device__ float g_Y[N_NODES * UNITS];             // emb @ kernel (12.8 MB)
__device__ int   g_count[N_NODES];                 // cursor == degree
__device__ int2  g_pairs[(long)N_NODES * CAP];     // (src, w bits), 25.6 MB

// ---------------------------------------------------------------------------
// 1) fused GEMM + scatter.
// Blocks [0, GEMM_BLOCKS): Y = emb @ kernel. 256 thr, 64 rows/block,
//   microtile 2 rows x 8 cols (8 f32x2 accs). sAT transposed (stride 68
//   floats = 272 B, 16B-aligned), sB weights. Per k: LDS.64 A + 2x LDS.128 B
//   + 8 fma.rn.f32x2.
// Blocks [GEMM_BLOCKS, +SCAT_BLOCKS): scatter 1024 edges/block into per-dst
//   buckets (4 edges/thread, int4/float4 loads).
// ---------------------------------------------------------------------------
__global__ void __launch_bounds__(256) k_fused(const float* __restrict__ emb,
                                               const float* __restrict__ kern,
                                               const int*   __restrict__ src,
                                               const int*   __restrict__ dst,
                                               const float* __restrict__ w) {
    __shared__ float sAT[D_FEAT][68];        // 17.4 KB (unused by scatter blocks)
    __shared__ float sB[D_FEAT * UNITS];     // 16 KB

    int tid = threadIdx.x;

    // ---------------- scatter role ----------------
    if (blockIdx.x >= GEMM_BLOCKS) {
        int q = (blockIdx.x - GEMM_BLOCKS) * 256 + tid;   // quad index
        if (q >= N_EDGES / 4) return;
        int4   s  = __ldg(reinterpret_cast<const int4*>(src) + q);
        int4   d  = __ldg(reinterpret_cast<const int4*>(dst) + q);
        float4 ww = __ldg(reinterpret_cast<const float4*>(w) + q);

        int   ds[4] = {d.x, d.y, d.z, d.w};
        int   ss[4] = {s.x, s.y, s.z, s.w};
        float ws[4] = {ww.x, ww.y, ww.z, ww.w};
        #pragma unroll
        for (int u = 0; u < 4; u++) {
            int p = atomicAdd(&g_count[ds[u]], 1);
            if (p < CAP)
                g_pairs[(long)ds[u] * CAP + p] =
                    make_int2(ss[u], __float_as_int(ws[u]));
        }
        return;
    }

    // ---------------- GEMM role ----------------
    int base = blockIdx.x * 64;

    // weights
    #pragma unroll
    for (int i = tid; i < D_FEAT * UNITS / 4; i += 256)
        reinterpret_cast<float4*>(sB)[i] =
            __ldg(reinterpret_cast<const float4*>(kern) + i);

    // A tile transposed: sAT[k][r] = emb[base+r][k]
    #pragma unroll
    for (int i = tid; i < 64 * 16; i += 256) {
        int r  = i >> 4;         // 0..63
        int kq = i & 15;         // float4 index along k
        int row = base + r;
        float4 v = (row < N_NODES)
                 ? __ldg(reinterpret_cast<const float4*>(emb + (long)row * D_FEAT) + kq)
                 : make_float4(0.f, 0.f, 0.f, 0.f);
        sAT[kq * 4 + 0][r] = v.x;
        sAT[kq * 4 + 1][r] = v.y;
        sAT[kq * 4 + 2][r] = v.z;
        sAT[kq * 4 + 3][r] = v.w;
    }
    __syncthreads();

    int rg = tid >> 3;   // 0..31 -> rows 2*rg, 2*rg+1
    int cg = tid & 7;    // 0..7  -> cols 8*cg .. 8*cg+7

    ull acc[2][4];
    #pragma unroll
    for (int i = 0; i < 2; i++)
        #pragma unroll
        for (int j = 0; j < 4; j++) acc[i][j] = 0ULL;

    #pragma unroll 8
    for (int k = 0; k < D_FEAT; k++) {
        float2 a = *reinterpret_cast<const float2*>(&sAT[k][rg * 2]);
        const float4* bp = reinterpret_cast<const float4*>(sB + k * UNITS + cg * 8);
        float4 b0 = bp[0];
        float4 b1 = bp[1];
        ull p0, p1, p2, p3;
        asm("mov.b64 %0, {%1, %2};" : "=l"(p0) : "f"(b0.x), "f"(b0.y));
        asm("mov.b64 %0, {%1, %2};" : "=l"(p1) : "f"(b0.z), "f"(b0.w));
        asm("mov.b64 %0, {%1, %2};" : "=l"(p2) : "f"(b1.x), "f"(b1.y));
        asm("mov.b64 %0, {%1, %2};" : "=l"(p3) : "f"(b1.z), "f"(b1.w));
        float ar[2] = {a.x, a.y};
        #pragma unroll
        for (int i = 0; i < 2; i++) {
            ull av;
            asm("mov.b64 %0, {%1, %1};" : "=l"(av) : "f"(ar[i]));
            asm("fma.rn.f32x2 %0, %1, %2, %0;" : "+l"(acc[i][0]) : "l"(av), "l"(p0));
            asm("fma.rn.f32x2 %0, %1, %2, %0;" : "+l"(acc[i][1]) : "l"(av), "l"(p1));
            asm("fma.rn.f32x2 %0, %1, %2, %0;" : "+l"(acc[i][2]) : "l"(av), "l"(p2));
            asm("fma.rn.f32x2 %0, %1, %2, %0;" : "+l"(acc[i][3]) : "l"(av), "l"(p3));
        }
    }

    #pragma unroll
    for (int i = 0; i < 2; i++) {
        int row = base + rg * 2 + i;
        if (row < N_NODES) {
            float x0,y0,x1,y1,x2,y2,x3,y3;
            asm("mov.b64 {%0, %1}, %2;" : "=f"(x0), "=f"(y0) : "l"(acc[i][0]));
            asm("mov.b64 {%0, %1}, %2;" : "=f"(x1), "=f"(y1) : "l"(acc[i][1]));
            asm("mov.b64 {%0, %1}, %2;" : "=f"(x2), "=f"(y2) : "l"(acc[i][2]));
            asm("mov.b64 {%0, %1}, %2;" : "=f"(x3), "=f"(y3) : "l"(acc[i][3]));
            float4* dst4 = reinterpret_cast<float4*>(g_Y + (long)row * UNITS + cg * 8);
            dst4[0] = make_float4(x0, y0, x1, y1);
            dst4[1] = make_float4(x2, y2, x3, y3);
        }
    }
}

// ---------------------------------------------------------------------------
// 2) aggregation + ReLU: warp per node, lane = column pair (f32x2 acc).
// Pairs loaded coalesced, broadcast via shfl; 8-way batched gathers (MLP=8).
// Tail: re-zero this node's counter for the next graph replay.
// ---------------------------------------------------------------------------
__global__ void __launch_bounds__(256) k_agg_relu(float* __restrict__ out) {
    int node = blockIdx.x * 8 + (threadIdx.x >> 5);
    if (node >= N_NODES) return;
    int lane = threadIdx.x & 31;

    int deg = min(__ldg(&g_count[node]), CAP);
    const int2* bucket = g_pairs + (long)node * CAP;

    ull acc = 0;

    for (int base = 0; base < deg; base += 32) {
        int j = base + lane;
        int2 pr = (j < deg) ? __ldg(bucket + j) : make_int2(0, 0);
        int cnt = min(deg - base, 32);

        int t = 0;
        for (; t + 8 <= cnt; t += 8) {
            int ssrc[8], wbit[8];
            ull y[8];
            #pragma unroll
            for (int u = 0; u < 8; u++) {
                ssrc[u] = __shfl_sync(0xffffffffu, pr.x, t + u);
                wbit[u] = __shfl_sync(0xffffffffu, pr.y, t + u);
            }
            #pragma unroll
            for (int u = 0; u < 8; u++)
                y[u] = __ldg(reinterpret_cast<const ull*>(
                           g_Y + (long)ssrc[u] * UNITS) + lane);
            #pragma unroll
            for (int u = 0; u < 8; u++) {
                ull wv;
                asm("mov.b64 %0, {%1, %1};" : "=l"(wv) : "r"(wbit[u]));
                asm("fma.rn.f32x2 %0, %1, %2, %0;" : "+l"(acc) : "l"(wv), "l"(y[u]));
            }
        }
        for (; t < cnt; t++) {
            int s  = __shfl_sync(0xffffffffu, pr.x, t);
            int wb = __shfl_sync(0xffffffffu, pr.y, t);
            ull y = __ldg(reinterpret_cast<const ull*>(
                        g_Y + (long)s * UNITS) + lane);
            ull wv;
            asm("mov.b64 %0, {%1, %1};" : "=l"(wv) : "r"(wb));
            asm("fma.rn.f32x2 %0, %1, %2, %0;" : "+l"(acc) : "l"(wv), "l"(y));
        }
    }

    float lo, hi;
    asm("mov.b64 {%0, %1}, %2;" : "=f"(lo), "=f"(hi) : "l"(acc));
    reinterpret_cast<float2*>(out)[(long)node * 32 + lane] =
        make_float2(fmaxf(lo, 0.f), fmaxf(hi, 0.f));

    // reset counter for next replay (degree already consumed by all lanes)
    if (lane == 0) g_count[node] = 0;
}

// ---------------------------------------------------------------------------
// Launch: 2 kernels total
// ---------------------------------------------------------------------------
extern "C" void kernel_launch(void* const* d_in, const int* in_sizes, int n_in,
                              void* d_out, int out_size) {
    const float* emb  = (const float*)d_in[0];
    const int*   src  = (const int*)  d_in[1];
    const int*   dst  = (const int*)  d_in[2];
    const float* w    = (const float*)d_in[3];
    const float* kern = (const float*)d_in[4];
    float* out        = (float*)d_out;

    k_fused<<<GEMM_BLOCKS + SCAT_BLOCKS, 256>>>(emb, kern, src, dst, w);
    k_agg_relu<<<(N_NODES + 7) / 8, 256>>>(out);
}